// round 3
// baseline (speedup 1.0000x reference)
#include <cuda_runtime.h>

// HybridReducedQ: quantum circuit reduces analytically to
//   q = cos(x_q[:,1] + p[1]) * cos(x_q[:,2] + p[2])
// then MLP 64->32->16->1 with ReLU.
//
// Round-3 design: warp-cooperative layer-1 (lane = neuron), f32x2 packed over
// row pairs, W1 held SPLATTED IN REGISTERS (128 GPRs) so the mainloop's only
// shared traffic is the broadcast x read. Static shared (27.7KB), 64-thr blocks.

#define WPB 2
#define NTHREADS (WPB * 32)
#define ROWS_PER_WARP 32
#define ROWS_PER_BLOCK (WPB * ROWS_PER_WARP)

typedef unsigned long long u64;

__device__ __forceinline__ u64 ffma2(u64 a, u64 b, u64 c) {
    u64 d;
    asm("fma.rn.f32x2 %0, %1, %2, %3;" : "=l"(d) : "l"(a), "l"(b), "l"(c));
    return d;
}
__device__ __forceinline__ u64 fadd2(u64 a, u64 b) {
    u64 d;
    asm("add.rn.f32x2 %0, %1, %2;" : "=l"(d) : "l"(a), "l"(b));
    return d;
}
__device__ __forceinline__ u64 pack2(float lo, float hi) {
    u64 d;
    asm("mov.b64 %0, {%1, %2};" : "=l"(d) : "f"(lo), "f"(hi));
    return d;
}
__device__ __forceinline__ float2 unpack2(u64 v) {
    float lo, hi;
    asm("mov.b64 {%0, %1}, %2;" : "=f"(lo), "=f"(hi) : "l"(v));
    return make_float2(lo, hi);
}

__global__ void __launch_bounds__(NTHREADS)
hybrid_mlp3_kernel(const float* __restrict__ x_q,
                   const float* __restrict__ x_c,
                   const float* __restrict__ q_params,
                   const float* __restrict__ w1,
                   const float* __restrict__ b1,
                   const float* __restrict__ w2,
                   const float* __restrict__ b2,
                   const float* __restrict__ w3,
                   const float* __restrict__ b3,
                   float* __restrict__ out,
                   int B) {
    // x2 : packed (rowEven, rowOdd) inputs, [warp][rowpair][feat]  16 KB
    // h1 : [warp][row][neuron+pad36]                                9 KB
    // w2s: splatted pairs (w2[2p][k], w2[2p+1][k]) [k][p]           2 KB
    __shared__ __align__(16) u64   sh_x2[WPB * 16 * 64];
    __shared__ __align__(16) float sh_h1[WPB * 32 * 36];
    __shared__ __align__(16) u64   sh_w2s[32 * 8];
    __shared__ __align__(16) u64   sh_b2s[8];

    const int tid  = threadIdx.x;
    const int lane = tid & 31;
    const int w    = tid >> 5;

    // ---- W1 row for this lane's neuron -> splatted registers (128 GPRs) ----
    u64 wreg[64];
    {
        const float4* wr = (const float4*)(w1 + lane * 64);
        #pragma unroll
        for (int v = 0; v < 16; v++) {
            float4 t = __ldg(wr + v);
            wreg[4 * v + 0] = pack2(t.x, t.x);
            wreg[4 * v + 1] = pack2(t.y, t.y);
            wreg[4 * v + 2] = pack2(t.z, t.z);
            wreg[4 * v + 3] = pack2(t.w, t.w);
        }
    }
    u64 b1s;
    { float bv = __ldg(b1 + lane); b1s = pack2(bv, bv); }

    // ---- Small weight staging (block-wide) ----
    for (int e = tid; e < 256; e += NTHREADS) {       // w2 [16][32] -> [k][pair]
        int k = e >> 3, p = e & 7;
        sh_w2s[k * 8 + p] = pack2(w2[(2 * p) * 32 + k], w2[(2 * p + 1) * 32 + k]);
    }
    if (tid < 8) sh_b2s[tid] = pack2(b2[2 * tid], b2[2 * tid + 1]);

    // ---- Per-warp x staging into packed row-pair layout ----
    const long long rowBase = (long long)blockIdx.x * ROWS_PER_BLOCK +
                              (long long)w * ROWS_PER_WARP;
    int rows = B - (int)rowBase;
    if (rows > ROWS_PER_WARP) rows = ROWS_PER_WARP;
    if (rows < 0) rows = 0;

    u64* xw = sh_x2 + w * 16 * 64;

    if (rows == ROWS_PER_WARP) {
        // warp tile of x_c is contiguous + 16B aligned: 504 float4s
        const float4* src = (const float4*)(x_c + rowBase * 63);
        #pragma unroll 1
        for (int idx = lane; idx < 504; idx += 32) {
            float4 v = src[idx];
            unsigned j0 = (unsigned)idx * 4u;
            #pragma unroll
            for (int t = 0; t < 4; t++) {
                unsigned j = j0 + t;
                unsigned r = j / 63u;
                unsigned f = j - r * 63u;
                ((float*)(xw + ((r >> 1) * 64 + 1 + f)))[r & 1] = (&v.x)[t];
            }
        }
    } else if (rows > 0) {
        const int nf = rows * 63;
        for (int j = lane; j < nf; j += 32) {
            unsigned r = (unsigned)j / 63u;
            unsigned f = (unsigned)j - r * 63u;
            ((float*)(xw + ((r >> 1) * 64 + 1 + f)))[r & 1] =
                x_c[rowBase * 63 + j];
        }
    }
    // quantum feature -> feature column 0
    const float p1 = __ldg(q_params + 1);
    const float p2 = __ldg(q_params + 2);
    if (lane < rows) {
        long long r = rowBase + lane;
        float q = __cosf(x_q[r * 3 + 1] + p1) * __cosf(x_q[r * 3 + 2] + p2);
        ((float*)(xw + ((lane >> 1) * 64)))[lane & 1] = q;
    }

    float w3r[16];
    #pragma unroll
    for (int j = 0; j < 16; j++) w3r[j] = __ldg(w3 + j);
    const float b3v = __ldg(b3);

    __syncthreads();

    // ---- Layer 1: lane = neuron; only shared traffic is broadcast x ----
    float* h1w = sh_h1 + w * 32 * 36;

    #pragma unroll 1
    for (int rp = 0; rp < 16; rp++) {
        const u64* xr = xw + rp * 64;
        u64 a0 = b1s;
        u64 a1 = pack2(0.0f, 0.0f);
        #pragma unroll
        for (int f = 0; f < 64; f += 4) {
            ulonglong2 xA = *(const ulonglong2*)(xr + f);
            ulonglong2 xB = *(const ulonglong2*)(xr + f + 2);
            a0 = ffma2(wreg[f + 0], xA.x, a0);
            a1 = ffma2(wreg[f + 1], xA.y, a1);
            a0 = ffma2(wreg[f + 2], xB.x, a0);
            a1 = ffma2(wreg[f + 3], xB.y, a1);
        }
        float2 h = unpack2(fadd2(a0, a1));
        h1w[(2 * rp) * 36 + lane]     = fmaxf(h.x, 0.0f);
        h1w[(2 * rp + 1) * 36 + lane] = fmaxf(h.y, 0.0f);
    }
    __syncwarp();

    // ---- Layers 2+3: lane = row ----
    const float* hr = h1w + lane * 36;
    u64 acc2[8];
    {
        ulonglong2 b01 = *(const ulonglong2*)(sh_b2s + 0);
        ulonglong2 b23 = *(const ulonglong2*)(sh_b2s + 2);
        ulonglong2 b45 = *(const ulonglong2*)(sh_b2s + 4);
        ulonglong2 b67 = *(const ulonglong2*)(sh_b2s + 6);
        acc2[0] = b01.x; acc2[1] = b01.y; acc2[2] = b23.x; acc2[3] = b23.y;
        acc2[4] = b45.x; acc2[5] = b45.y; acc2[6] = b67.x; acc2[7] = b67.y;
    }
    #pragma unroll
    for (int kk = 0; kk < 8; kk++) {
        float4 hv = *(const float4*)(hr + kk * 4);
        #pragma unroll
        for (int t = 0; t < 4; t++) {
            int k = kk * 4 + t;
            u64 hs = pack2((&hv.x)[t], (&hv.x)[t]);
            const u64* w2row = sh_w2s + k * 8;
            ulonglong2 w01 = *(const ulonglong2*)(w2row + 0);
            ulonglong2 w23 = *(const ulonglong2*)(w2row + 2);
            ulonglong2 w45 = *(const ulonglong2*)(w2row + 4);
            ulonglong2 w67 = *(const ulonglong2*)(w2row + 6);
            acc2[0] = ffma2(w01.x, hs, acc2[0]);
            acc2[1] = ffma2(w01.y, hs, acc2[1]);
            acc2[2] = ffma2(w23.x, hs, acc2[2]);
            acc2[3] = ffma2(w23.y, hs, acc2[3]);
            acc2[4] = ffma2(w45.x, hs, acc2[4]);
            acc2[5] = ffma2(w45.y, hs, acc2[5]);
            acc2[6] = ffma2(w67.x, hs, acc2[6]);
            acc2[7] = ffma2(w67.y, hs, acc2[7]);
        }
    }
    float res = b3v;
    #pragma unroll
    for (int p = 0; p < 8; p++) {
        float2 v = unpack2(acc2[p]);
        res = fmaf(fmaxf(v.x, 0.0f), w3r[2 * p], res);
        res = fmaf(fmaxf(v.y, 0.0f), w3r[2 * p + 1], res);
    }
    if (lane < rows) out[rowBase + lane] = res;
}

extern "C" void kernel_launch(void* const* d_in, const int* in_sizes, int n_in,
                              void* d_out, int out_size) {
    const float* x_q      = (const float*)d_in[0];
    const float* x_c      = (const float*)d_in[1];
    const float* q_params = (const float*)d_in[2];
    const float* w1       = (const float*)d_in[3];
    const float* b1       = (const float*)d_in[4];
    const float* w2       = (const float*)d_in[5];
    const float* b2       = (const float*)d_in[6];
    const float* w3       = (const float*)d_in[7];
    const float* b3       = (const float*)d_in[8];
    float* out = (float*)d_out;

    const int B = in_sizes[0] / 3;
    const int grid = (B + ROWS_PER_BLOCK - 1) / ROWS_PER_BLOCK;
    hybrid_mlp3_kernel<<<grid, NTHREADS>>>(
        x_q, x_c, q_params, w1, b1, w2, b2, w3, b3, out, B);
}

// round 6
// speedup vs baseline: 1.1559x; 1.1559x over previous
#include <cuda_runtime.h>

// HybridReducedQ: quantum circuit reduces analytically to
//   q = cos(x_q[:,1] + p[1]) * cos(x_q[:,2] + p[2])
// then MLP 64->32->16->1 with ReLU.
//
// Round-6: round-4 design with the crash fixed. Rounds 4/5 "container failed"
// was a misaligned ld.global.v2.f32 on x_q (stride-3 rows: (3r+1)*4 % 8 == 4
// for even r) -> err716 on half the lanes. Replaced with scalar loads.
//
// Design: lane=neuron layer-1, f32x2 packed over row pairs, W1 streamed
// through registers in 4 feature-quarters (peak ~90 regs, no spill),
// coalesced LDG + packed STS.64 staging, layers 2+3 with lane=row.

#define WPB 2
#define NTHREADS (WPB * 32)
#define ROWS_PER_WARP 32
#define ROWS_PER_BLOCK (WPB * ROWS_PER_WARP)

typedef unsigned long long u64;

__device__ __forceinline__ u64 ffma2(u64 a, u64 b, u64 c) {
    u64 d;
    asm("fma.rn.f32x2 %0, %1, %2, %3;" : "=l"(d) : "l"(a), "l"(b), "l"(c));
    return d;
}
__device__ __forceinline__ u64 fadd2(u64 a, u64 b) {
    u64 d;
    asm("add.rn.f32x2 %0, %1, %2;" : "=l"(d) : "l"(a), "l"(b));
    return d;
}
__device__ __forceinline__ u64 pack2(float lo, float hi) {
    u64 d;
    asm("mov.b64 %0, {%1, %2};" : "=l"(d) : "f"(lo), "f"(hi));
    return d;
}
__device__ __forceinline__ float2 unpack2(u64 v) {
    float lo, hi;
    asm("mov.b64 {%0, %1}, %2;" : "=f"(lo), "=f"(hi) : "l"(v));
    return make_float2(lo, hi);
}

__global__ void __launch_bounds__(NTHREADS)
hybrid_mlp6_kernel(const float* __restrict__ x_q,
                   const float* __restrict__ x_c,
                   const float* __restrict__ q_params,
                   const float* __restrict__ w1,
                   const float* __restrict__ b1,
                   const float* __restrict__ w2,
                   const float* __restrict__ b2,
                   const float* __restrict__ w3,
                   const float* __restrict__ b3,
                   float* __restrict__ out,
                   int B) {
    // x2 : (rowEven,rowOdd) input pairs [warp][rowpair][feat]   16 KB
    // h1 : [warp][row][neuron], pad 36                            9 KB
    // w2s: splatted pairs (w2[2p][k], w2[2p+1][k]) [k][p]         2 KB
    __shared__ __align__(16) u64   sh_x2[WPB * 16 * 64];
    __shared__ __align__(16) float sh_h1[WPB * 32 * 36];
    __shared__ __align__(16) u64   sh_w2s[32 * 8];
    __shared__ __align__(16) u64   sh_b2s[8];

    const int tid  = threadIdx.x;
    const int lane = tid & 31;
    const int w    = tid >> 5;

    // ---- Small weight staging (block-wide) ----
    for (int e = tid; e < 256; e += NTHREADS) {       // w2 [16][32] -> [k][pair]
        int k = e >> 3, p = e & 7;
        sh_w2s[k * 8 + p] = pack2(w2[(2 * p) * 32 + k], w2[(2 * p + 1) * 32 + k]);
    }
    if (tid < 8) sh_b2s[tid] = pack2(b2[2 * tid], b2[2 * tid + 1]);

    // ---- Per-warp x staging: packed (rowA,rowB) pairs, no div, no scatter --
    const long long rowBase = (long long)blockIdx.x * ROWS_PER_BLOCK +
                              (long long)w * ROWS_PER_WARP;
    int rows = B - (int)rowBase;
    if (rows > ROWS_PER_WARP) rows = ROWS_PER_WARP;
    if (rows < 0) rows = 0;

    u64* xw = sh_x2 + w * 16 * 64;
    const float p1 = __ldg(q_params + 1);
    const float p2 = __ldg(q_params + 2);

    if (rows == ROWS_PER_WARP) {
        // quantum feature -> slot 0 of each rowpair (component = row parity).
        // SCALAR loads only: x_q rows have stride 3, a float2 here is
        // misaligned for even rows (this crashed rounds 4/5).
        {
            long long r = rowBase + lane;
            float xq1 = __ldg(x_q + r * 3 + 1);
            float xq2 = __ldg(x_q + r * 3 + 2);
            float q = __cosf(xq1 + p1) * __cosf(xq2 + p2);
            ((float*)(xw + ((lane >> 1) * 64)))[lane & 1] = q;
        }
        // x_c pairs: lane = feature index; coalesced LDG.32, packed STS.64
        const float* xc = x_c + rowBase * 63;
        #pragma unroll 2
        for (int rp = 0; rp < 16; rp++) {
            const float* rowA = xc + (2 * rp) * 63;
            const float* rowB = rowA + 63;
            if (lane >= 1) {                       // feature slots 1..31
                xw[rp * 64 + lane] = pack2(rowA[lane - 1], rowB[lane - 1]);
            }
            {                                       // feature slots 32..63
                xw[rp * 64 + 32 + lane] =
                    pack2(rowA[31 + lane], rowB[31 + lane]);
            }
        }
    } else {
        // tail: zero-fill then guarded scalar staging
        for (int j = lane; j < 16 * 64; j += 32) xw[j] = 0ull;
        __syncwarp();
        for (int j = lane; j < rows * 63; j += 32) {
            unsigned r = (unsigned)j / 63u;
            unsigned f = (unsigned)j - r * 63u;
            ((float*)(xw + ((r >> 1) * 64 + 1 + f)))[r & 1] =
                x_c[rowBase * 63 + j];
        }
        if (lane < rows) {
            long long r = rowBase + lane;
            float q = __cosf(__ldg(x_q + r * 3 + 1) + p1) *
                      __cosf(__ldg(x_q + r * 3 + 2) + p2);
            ((float*)(xw + ((lane >> 1) * 64)))[lane & 1] = q;
        }
    }

    u64 b1s;
    { float bv = __ldg(b1 + lane); b1s = pack2(bv, bv); }
    float w3r[16];
    #pragma unroll
    for (int j = 0; j < 16; j++) w3r[j] = __ldg(w3 + j);
    const float b3v = __ldg(b3);

    __syncthreads();

    // ---- Layer 1: lane = neuron; W1 in 4 feature-quarters of 16 ----
    u64 part[16];
    #pragma unroll
    for (int rp = 0; rp < 16; rp++) part[rp] = b1s;

    const float4* wrow = (const float4*)(w1 + lane * 64);
    const u64 zero2 = pack2(0.0f, 0.0f);

    #pragma unroll
    for (int fq = 0; fq < 4; fq++) {
        // load + splat this quarter's 16 weights (32 regs live)
        float4 wa = __ldg(wrow + 4 * fq + 0);
        float4 wb = __ldg(wrow + 4 * fq + 1);
        float4 wc = __ldg(wrow + 4 * fq + 2);
        float4 wd = __ldg(wrow + 4 * fq + 3);
        u64 ws[16];
        ws[0]  = pack2(wa.x, wa.x); ws[1]  = pack2(wa.y, wa.y);
        ws[2]  = pack2(wa.z, wa.z); ws[3]  = pack2(wa.w, wa.w);
        ws[4]  = pack2(wb.x, wb.x); ws[5]  = pack2(wb.y, wb.y);
        ws[6]  = pack2(wb.z, wb.z); ws[7]  = pack2(wb.w, wb.w);
        ws[8]  = pack2(wc.x, wc.x); ws[9]  = pack2(wc.y, wc.y);
        ws[10] = pack2(wc.z, wc.z); ws[11] = pack2(wc.w, wc.w);
        ws[12] = pack2(wd.x, wd.x); ws[13] = pack2(wd.y, wd.y);
        ws[14] = pack2(wd.z, wd.z); ws[15] = pack2(wd.w, wd.w);

        #pragma unroll
        for (int rp = 0; rp < 16; rp++) {
            const u64* xr = xw + rp * 64 + fq * 16;
            u64 a0 = part[rp];
            u64 a1 = zero2;
            #pragma unroll
            for (int v = 0; v < 4; v++) {
                ulonglong2 xA = *(const ulonglong2*)(xr + 4 * v);
                ulonglong2 xB = *(const ulonglong2*)(xr + 4 * v + 2);
                a0 = ffma2(ws[4 * v + 0], xA.x, a0);
                a1 = ffma2(ws[4 * v + 1], xA.y, a1);
                a0 = ffma2(ws[4 * v + 2], xB.x, a0);
                a1 = ffma2(ws[4 * v + 3], xB.y, a1);
            }
            part[rp] = fadd2(a0, a1);
        }
    }

    // ReLU + transpose through shared
    float* h1w = sh_h1 + w * 32 * 36;
    #pragma unroll
    for (int rp = 0; rp < 16; rp++) {
        float2 h = unpack2(part[rp]);
        h1w[(2 * rp) * 36 + lane]     = fmaxf(h.x, 0.0f);
        h1w[(2 * rp + 1) * 36 + lane] = fmaxf(h.y, 0.0f);
    }
    __syncwarp();

    // ---- Layers 2+3: lane = row ----
    const float* hr = h1w + lane * 36;
    u64 acc2[8];
    {
        ulonglong2 b01 = *(const ulonglong2*)(sh_b2s + 0);
        ulonglong2 b23 = *(const ulonglong2*)(sh_b2s + 2);
        ulonglong2 b45 = *(const ulonglong2*)(sh_b2s + 4);
        ulonglong2 b67 = *(const ulonglong2*)(sh_b2s + 6);
        acc2[0] = b01.x; acc2[1] = b01.y; acc2[2] = b23.x; acc2[3] = b23.y;
        acc2[4] = b45.x; acc2[5] = b45.y; acc2[6] = b67.x; acc2[7] = b67.y;
    }
    #pragma unroll
    for (int kk = 0; kk < 8; kk++) {
        float4 hv = *(const float4*)(hr + kk * 4);
        #pragma unroll
        for (int t = 0; t < 4; t++) {
            int k = kk * 4 + t;
            u64 hs = pack2((&hv.x)[t], (&hv.x)[t]);
            const u64* w2row = sh_w2s + k * 8;
            ulonglong2 w01 = *(const ulonglong2*)(w2row + 0);
            ulonglong2 w23 = *(const ulonglong2*)(w2row + 2);
            ulonglong2 w45 = *(const ulonglong2*)(w2row + 4);
            ulonglong2 w67 = *(const ulonglong2*)(w2row + 6);
            acc2[0] = ffma2(w01.x, hs, acc2[0]);
            acc2[1] = ffma2(w01.y, hs, acc2[1]);
            acc2[2] = ffma2(w23.x, hs, acc2[2]);
            acc2[3] = ffma2(w23.y, hs, acc2[3]);
            acc2[4] = ffma2(w45.x, hs, acc2[4]);
            acc2[5] = ffma2(w45.y, hs, acc2[5]);
            acc2[6] = ffma2(w67.x, hs, acc2[6]);
            acc2[7] = ffma2(w67.y, hs, acc2[7]);
        }
    }
    float res = b3v;
    #pragma unroll
    for (int p = 0; p < 8; p++) {
        float2 v = unpack2(acc2[p]);
        res = fmaf(fmaxf(v.x, 0.0f), w3r[2 * p], res);
        res = fmaf(fmaxf(v.y, 0.0f), w3r[2 * p + 1], res);
    }
    if (lane < rows) out[rowBase + lane] = res;
}

extern "C" void kernel_launch(void* const* d_in, const int* in_sizes, int n_in,
                              void* d_out, int out_size) {
    const float* x_q      = (const float*)d_in[0];
    const float* x_c      = (const float*)d_in[1];
    const float* q_params = (const float*)d_in[2];
    const float* w1       = (const float*)d_in[3];
    const float* b1       = (const float*)d_in[4];
    const float* w2       = (const float*)d_in[5];
    const float* b2       = (const float*)d_in[6];
    const float* w3       = (const float*)d_in[7];
    const float* b3       = (const float*)d_in[8];
    float* out = (float*)d_out;

    const int B = in_sizes[0] / 3;
    const int grid = (B + ROWS_PER_BLOCK - 1) / ROWS_PER_BLOCK;
    hybrid_mlp6_kernel<<<grid, NTHREADS>>>(
        x_q, x_c, q_params, w1, b1, w2, b2, w3, b3, out, B);
}

// round 8
// speedup vs baseline: 2.3616x; 2.0432x over previous
#include <cuda_runtime.h>
#include <cstdint>

// HybridReducedQ: q = cos(xq1+p1)*cos(xq2+p2); MLP 64->32->16->1 (ReLU).
//
// Round-8: full MLP on mma.sync (HMMA, compiles for plain sm_100 -- tcgen05
// needs sm_100a which this harness's ptxas target rejects). bf16 hi/lo split,
// 3 passes per layer (~1e-5 rel err). All operand movement is per-lane
// distinct (ldmatrix / fragment loads) -- no broadcast LDS, which round-6
// measured at 64 cyc/row of pure l1tex writeback. Layer1 C fragments convert
// in-register to layer2 A fragments (C m16n8 layout == A m16k16 layout), so
// the h1 transpose vanishes. Layer3 = 2x shfl.bfly reduce.

#define NTHREADS 128
#define CTA_ROWS 128

typedef unsigned int u32;

// shared byte offsets (static, 40KB)
#define SH_XHI 0        // 4 warps x 32 rows x 64 bf16 (swizzled), 16KB
#define SH_XLO 16384
#define SH_W1H 32768    // 32 x 64 bf16 swizzled, 4KB
#define SH_W1L 36864
#define SH_TOTAL 40960

__device__ __forceinline__ u32 cvt_bf16x2(float v0, float v1) {
    u32 d;  // v0 -> low half, v1 -> high half
    asm("cvt.rn.bf16x2.f32 %0, %1, %2;" : "=r"(d) : "f"(v1), "f"(v0));
    return d;
}
__device__ __forceinline__ u32 smem_u32(const void* p) {
    u32 a;
    asm("{ .reg .u64 t; cvta.to.shared.u64 t, %1; cvt.u32.u64 %0, t; }"
        : "=r"(a) : "l"(p));
    return a;
}
__device__ __forceinline__ void ldsm_x4(u32 addr, u32& r0, u32& r1, u32& r2,
                                        u32& r3) {
    asm volatile("ldmatrix.sync.aligned.m8n8.x4.shared.b16 {%0,%1,%2,%3}, [%4];"
                 : "=r"(r0), "=r"(r1), "=r"(r2), "=r"(r3) : "r"(addr));
}
__device__ __forceinline__ void ldsm_x2(u32 addr, u32& r0, u32& r1) {
    asm volatile("ldmatrix.sync.aligned.m8n8.x2.shared.b16 {%0,%1}, [%2];"
                 : "=r"(r0), "=r"(r1) : "r"(addr));
}
__device__ __forceinline__ void mma_bf16(float* c, const u32* a, u32 b0,
                                         u32 b1) {
    asm volatile(
        "mma.sync.aligned.m16n8k16.row.col.f32.bf16.bf16.f32 "
        "{%0,%1,%2,%3}, {%4,%5,%6,%7}, {%8,%9}, {%0,%1,%2,%3};"
        : "+f"(c[0]), "+f"(c[1]), "+f"(c[2]), "+f"(c[3])
        : "r"(a[0]), "r"(a[1]), "r"(a[2]), "r"(a[3]), "r"(b0), "r"(b1));
}
__device__ __forceinline__ void split_lo(u32 hi, float f0, float f1, u32& lo) {
    float f0h = __uint_as_float(hi << 16);
    float f1h = __uint_as_float(hi & 0xFFFF0000u);
    lo = cvt_bf16x2(f0 - f0h, f1 - f1h);
}

__global__ void __launch_bounds__(NTHREADS)
hybrid_hmma_kernel(const float* __restrict__ x_q,
                   const float* __restrict__ x_c,
                   const float* __restrict__ q_params,
                   const float* __restrict__ w1,
                   const float* __restrict__ b1,
                   const float* __restrict__ w2,
                   const float* __restrict__ b2,
                   const float* __restrict__ w3,
                   const float* __restrict__ b3,
                   float* __restrict__ out,
                   int B) {
    __shared__ __align__(128) unsigned char sh[SH_TOTAL];

    const int tid = threadIdx.x;
    const int lane = tid & 31;
    const int w = tid >> 5;
    const int tg = lane & 3;         // thread-in-group
    const int g = lane >> 2;         // group id (row within 8)
    const int l7 = lane & 7;

    const long long rowBase = (long long)blockIdx.x * CTA_ROWS;
    const long long warpRow = rowBase + w * 32;

    const float p1 = __ldg(q_params + 1);
    const float p2 = __ldg(q_params + 2);

    // ---- q pre-pass: lane = row (kept in register, distributed via shfl) --
    float qreg;
    {
        long long r = warpRow + lane;
        if (r >= B) r = B - 1;
        qreg = __cosf(__ldg(x_q + r * 3 + 1) + p1) *
               __cosf(__ldg(x_q + r * 3 + 2) + p2);
    }

    // ---- W1 staging: [32 neurons][64 k] bf16 hi/lo, swizzled rows ----
    {
        const int n = tid >> 2, kq = tid & 3;
        const float* src = w1 + n * 64 + kq * 16;
        float v[16];
        #pragma unroll
        for (int j = 0; j < 4; j++) {
            float4 t4 = __ldg((const float4*)src + j);
            v[4 * j] = t4.x; v[4 * j + 1] = t4.y;
            v[4 * j + 2] = t4.z; v[4 * j + 3] = t4.w;
        }
        u32 hi[8], lo[8];
        #pragma unroll
        for (int j = 0; j < 8; j++) {
            hi[j] = cvt_bf16x2(v[2 * j], v[2 * j + 1]);
            split_lo(hi[j], v[2 * j], v[2 * j + 1], lo[j]);
        }
        const u32 base = (u32)(n * 128);
        const u32 c0 = (u32)(((kq * 2) ^ (n & 7)) << 4);
        const u32 c1 = (u32)(((kq * 2 + 1) ^ (n & 7)) << 4);
        *(uint4*)(sh + SH_W1H + base + c0) = make_uint4(hi[0], hi[1], hi[2], hi[3]);
        *(uint4*)(sh + SH_W1H + base + c1) = make_uint4(hi[4], hi[5], hi[6], hi[7]);
        *(uint4*)(sh + SH_W1L + base + c0) = make_uint4(lo[0], lo[1], lo[2], lo[3]);
        *(uint4*)(sh + SH_W1L + base + c1) = make_uint4(lo[4], lo[5], lo[6], lo[7]);
    }

    // ---- x staging: per-warp 32 rows x 64 feats bf16 hi/lo, swizzled ----
    // lane t owns feats {2t, 2t+1}; feat 0 = q, feats 1..63 = x_c[0..62].
    {
        unsigned char* xh = sh + SH_XHI + w * 4096;
        unsigned char* xl = sh + SH_XLO + w * 4096;
        const int t = lane;
        const u32 inlane = (u32)((t & 3) * 4);
        #pragma unroll 4
        for (int r = 0; r < 32; r++) {
            long long rg = warpRow + r;
            if (rg >= B) rg = B - 1;
            const float* xr = x_c + rg * 63;
            float va = __ldg(xr + (t ? 2 * t - 1 : 0));
            float vb = __ldg(xr + 2 * t);
            float qv = __shfl_sync(0xffffffffu, qreg, r);
            float f0 = (t == 0) ? qv : va;
            u32 hi = cvt_bf16x2(f0, vb);
            u32 lo; split_lo(hi, f0, vb, lo);
            u32 soff = (u32)(r * 128 + ((((t >> 2)) ^ (r & 7)) << 4)) + inlane;
            *(u32*)(xh + soff) = hi;
            *(u32*)(xl + soff) = lo;
        }
    }
    __syncthreads();

    const u32 shb = smem_u32(sh);
    const u32 XHIu = shb + SH_XHI + w * 4096;
    const u32 XLOu = shb + SH_XLO + w * 4096;
    const u32 W1Hu = shb + SH_W1H;
    const u32 W1Lu = shb + SH_W1L;

    // ---- resident W1-hi fragments: [ntile 4][kstep 4][2 regs] ----
    const int wmat = (lane >> 3) & 1;
    u32 wh[4][4][2];
    #pragma unroll
    for (int nt = 0; nt < 4; nt++)
        #pragma unroll
        for (int ks = 0; ks < 4; ks++) {
            u32 a = W1Hu + (u32)((nt * 8 + l7) * 128 +
                                 (((ks * 2 + wmat) ^ l7) << 4));
            ldsm_x2(a, wh[nt][ks][0], wh[nt][ks][1]);
        }

    // A-fragment lane addressing constants
    const int amat = lane >> 3;                 // 0..3
    const int arl = ((amat & 1) << 3) + l7;     // row within m16 tile
    const int aca = amat >> 1;                  // chunk add (k-half)

    // ---- Layer 1: [32x64] @ [64x32], 3-pass bf16 split ----
    float acc[2][4][4];
    #pragma unroll
    for (int m = 0; m < 2; m++)
        #pragma unroll
        for (int nt = 0; nt < 4; nt++)
            #pragma unroll
            for (int j = 0; j < 4; j++) acc[m][nt][j] = 0.0f;

    #pragma unroll
    for (int ks = 0; ks < 4; ks++) {
        u32 ah[2][4], al[2][4];
        #pragma unroll
        for (int m = 0; m < 2; m++) {
            u32 aoff = (u32)((m * 16 + arl) * 128 +
                             (((2 * ks + aca) ^ l7) << 4));
            ldsm_x4(XHIu + aoff, ah[m][0], ah[m][1], ah[m][2], ah[m][3]);
            ldsm_x4(XLOu + aoff, al[m][0], al[m][1], al[m][2], al[m][3]);
        }
        #pragma unroll
        for (int nt = 0; nt < 4; nt++) {
            u32 wl0, wl1;
            ldsm_x2(W1Lu + (u32)((nt * 8 + l7) * 128 +
                                 (((ks * 2 + wmat) ^ l7) << 4)), wl0, wl1);
            #pragma unroll
            for (int m = 0; m < 2; m++) {
                mma_bf16(acc[m][nt], ah[m], wh[nt][ks][0], wh[nt][ks][1]);
                mma_bf16(acc[m][nt], al[m], wh[nt][ks][0], wh[nt][ks][1]);
                mma_bf16(acc[m][nt], ah[m], wl0, wl1);
            }
        }
    }

    // ---- bias + ReLU; C1 fragments -> A2 fragments IN REGISTER ----
    // C frag: c0=(g,2tg) c1=(g,2tg+1) c2=(g+8,2tg) c3=(g+8,2tg+1)
    // A2 m16k16 (k=neurons): kstep K covers neurons 16K..16K+15;
    //   regs 0,1 <- nt=2K (cols 0-7); regs 2,3 <- nt=2K+1 (cols 8-15).
    float b1c[4][2];
    #pragma unroll
    for (int nt = 0; nt < 4; nt++) {
        b1c[nt][0] = __ldg(b1 + nt * 8 + 2 * tg);
        b1c[nt][1] = __ldg(b1 + nt * 8 + 2 * tg + 1);
    }
    u32 a2h[2][2][4], a2l[2][2][4];
    #pragma unroll
    for (int m = 0; m < 2; m++)
        #pragma unroll
        for (int nt = 0; nt < 4; nt++) {
            float v0 = fmaxf(acc[m][nt][0] + b1c[nt][0], 0.0f);
            float v1 = fmaxf(acc[m][nt][1] + b1c[nt][1], 0.0f);
            float v2 = fmaxf(acc[m][nt][2] + b1c[nt][0], 0.0f);
            float v3 = fmaxf(acc[m][nt][3] + b1c[nt][1], 0.0f);
            const int K = nt >> 1, rbase = (nt & 1) * 2;
            u32 h0 = cvt_bf16x2(v0, v1);
            u32 h1r = cvt_bf16x2(v2, v3);
            a2h[m][K][rbase + 0] = h0;
            a2h[m][K][rbase + 1] = h1r;
            split_lo(h0, v0, v1, a2l[m][K][rbase + 0]);
            split_lo(h1r, v2, v3, a2l[m][K][rbase + 1]);
        }

    // ---- W2 fragments: b0=(k=2tg..,n=g), b1=(k+8..) per [nt2 2][K 2] ----
    u32 w2h[2][2][2], w2l[2][2][2];
    #pragma unroll
    for (int nt2 = 0; nt2 < 2; nt2++)
        #pragma unroll
        for (int K = 0; K < 2; K++) {
            const float* wr = w2 + (nt2 * 8 + g) * 32 + K * 16 + 2 * tg;
            float2 f01 = *(const float2*)wr;        // 8B aligned (2tg even)
            float2 f23 = *(const float2*)(wr + 8);
            w2h[nt2][K][0] = cvt_bf16x2(f01.x, f01.y);
            w2h[nt2][K][1] = cvt_bf16x2(f23.x, f23.y);
            split_lo(w2h[nt2][K][0], f01.x, f01.y, w2l[nt2][K][0]);
            split_lo(w2h[nt2][K][1], f23.x, f23.y, w2l[nt2][K][1]);
        }

    // ---- Layer 2: [32x32] @ [32x16], 3-pass split ----
    float acc2[2][2][4];
    #pragma unroll
    for (int m = 0; m < 2; m++)
        #pragma unroll
        for (int nt2 = 0; nt2 < 2; nt2++)
            #pragma unroll
            for (int j = 0; j < 4; j++) acc2[m][nt2][j] = 0.0f;
    #pragma unroll
    for (int K = 0; K < 2; K++)
        #pragma unroll
        for (int nt2 = 0; nt2 < 2; nt2++)
            #pragma unroll
            for (int m = 0; m < 2; m++) {
                mma_bf16(acc2[m][nt2], a2h[m][K], w2h[nt2][K][0], w2h[nt2][K][1]);
                mma_bf16(acc2[m][nt2], a2l[m][K], w2h[nt2][K][0], w2h[nt2][K][1]);
                mma_bf16(acc2[m][nt2], a2h[m][K], w2l[nt2][K][0], w2l[nt2][K][1]);
            }

    // ---- Layer 3 + epilogue: per-lane partials, shfl.bfly quad reduce ----
    float w3c[4], b2c[2][2];
    w3c[0] = __ldg(w3 + 2 * tg);     w3c[1] = __ldg(w3 + 2 * tg + 1);
    w3c[2] = __ldg(w3 + 8 + 2 * tg); w3c[3] = __ldg(w3 + 9 + 2 * tg);
    b2c[0][0] = __ldg(b2 + 2 * tg);     b2c[0][1] = __ldg(b2 + 2 * tg + 1);
    b2c[1][0] = __ldg(b2 + 8 + 2 * tg); b2c[1][1] = __ldg(b2 + 9 + 2 * tg);
    const float b3v = __ldg(b3);

    #pragma unroll
    for (int m = 0; m < 2; m++) {
        float s0 = 0.0f, s8 = 0.0f;
        #pragma unroll
        for (int nt2 = 0; nt2 < 2; nt2++) {
            s0 = fmaf(fmaxf(acc2[m][nt2][0] + b2c[nt2][0], 0.0f), w3c[nt2 * 2 + 0], s0);
            s0 = fmaf(fmaxf(acc2[m][nt2][1] + b2c[nt2][1], 0.0f), w3c[nt2 * 2 + 1], s0);
            s8 = fmaf(fmaxf(acc2[m][nt2][2] + b2c[nt2][0], 0.0f), w3c[nt2 * 2 + 0], s8);
            s8 = fmaf(fmaxf(acc2[m][nt2][3] + b2c[nt2][1], 0.0f), w3c[nt2 * 2 + 1], s8);
        }
        s0 += __shfl_xor_sync(0xffffffffu, s0, 1);
        s0 += __shfl_xor_sync(0xffffffffu, s0, 2);
        s8 += __shfl_xor_sync(0xffffffffu, s8, 1);
        s8 += __shfl_xor_sync(0xffffffffu, s8, 2);
        if (tg == 0) {
            long long r0 = warpRow + m * 16 + g;
            if (r0 < B)     out[r0] = s0 + b3v;
            if (r0 + 8 < B) out[r0 + 8] = s8 + b3v;
        }
    }
}

extern "C" void kernel_launch(void* const* d_in, const int* in_sizes, int n_in,
                              void* d_out, int out_size) {
    const float* x_q      = (const float*)d_in[0];
    const float* x_c      = (const float*)d_in[1];
    const float* q_params = (const float*)d_in[2];
    const float* w1       = (const float*)d_in[3];
    const float* b1       = (const float*)d_in[4];
    const float* w2       = (const float*)d_in[5];
    const float* b2       = (const float*)d_in[6];
    const float* w3       = (const float*)d_in[7];
    const float* b3       = (const float*)d_in[8];
    float* out = (float*)d_out;

    const int B = in_sizes[0] / 3;
    const int grid = (B + CTA_ROWS - 1) / CTA_ROWS;
    hybrid_hmma_kernel<<<grid, NTHREADS>>>(
        x_q, x_c, q_params, w1, b1, w2, b2, w3, b3, out, B);
}